// round 6
// baseline (speedup 1.0000x reference)
#include <cuda_runtime.h>

#define EPS 1e-5f

// ---------------- scratch (device globals; no allocations allowed) ----------
static __device__ float g_act1[256*64*32*32];   // 64 MB
static __device__ float g_act2[256*128*16*16];  // 32 MB
static __device__ float g_act3[256*256*8*8];    // 16 MB
static __device__ float g_M[256*64*50];         // 3.3 MB
static __device__ float g_ob[256*64];
static __device__ float g_mb[256*4160];

__device__ __forceinline__ float lrelu(float v) { return v >= 0.f ? v : 0.2f*v; }

// ============================================================================
// conv1: x(256,3,64,64) * w1(64,3,5,5) s2 p2 -> (256,64,32,32), IN + lrelu
// block = (c_out, n); 256 threads; each thread computes a 2x2 output quad.
// ============================================================================
__global__ void __launch_bounds__(256) conv1_kernel(
    const float* __restrict__ x, const float* __restrict__ w,
    const float* __restrict__ b, const float* __restrict__ g,
    const float* __restrict__ be)
{
    const int c_out = blockIdx.x;
    const int n = blockIdx.y;
    const int tid = threadIdx.x;
    const int by = tid >> 4, bx = tid & 15;   // 16x16 quads over 32x32 plane

    __shared__ float s_in[68*68];             // padded 64+2+2
    __shared__ float s_w[75];
    __shared__ float s_r[256];
    __shared__ float s_q[256];

    if (tid < 75) s_w[tid] = w[c_out*75 + tid];

    float acc[4] = {0.f, 0.f, 0.f, 0.f};

    for (int c = 0; c < 3; ++c) {
        __syncthreads();
        const float* xp = x + ((n*3 + c) << 12);
        for (int idx = tid; idx < 68*68; idx += 256) {
            int sy = idx / 68 - 2;
            int sx = idx - (sy + 2)*68 - 2;
            float v = 0.f;
            if (sy >= 0 && sy < 64 && sx >= 0 && sx < 64) v = xp[(sy << 6) + sx];
            s_in[idx] = v;
        }
        __syncthreads();
        const float* tin = s_in + (by*4)*68 + bx*4;
        const float* tw  = s_w + c*25;
        #pragma unroll
        for (int ky = 0; ky < 5; ++ky) {
            #pragma unroll
            for (int kx = 0; kx < 5; ++kx) {
                float wv = tw[ky*5 + kx];
                acc[0] += tin[ky*68 + kx]       * wv;
                acc[1] += tin[ky*68 + kx + 2]   * wv;
                acc[2] += tin[(ky+2)*68 + kx]   * wv;
                acc[3] += tin[(ky+2)*68 + kx+2] * wv;
            }
        }
    }

    float bc = b[c_out];
    float lv = 0.f, lq = 0.f;
    #pragma unroll
    for (int p = 0; p < 4; ++p) { acc[p] += bc; lv += acc[p]; lq += acc[p]*acc[p]; }

    __syncthreads();
    s_r[tid] = lv; s_q[tid] = lq;
    __syncthreads();
    for (int s = 128; s > 0; s >>= 1) {
        if (tid < s) { s_r[tid] += s_r[tid+s]; s_q[tid] += s_q[tid+s]; }
        __syncthreads();
    }
    float mean = s_r[0] * (1.f/1024.f);
    float var  = fmaxf(s_q[0] * (1.f/1024.f) - mean*mean, 0.f);
    float scale = g[c_out] * rsqrtf(var + EPS);
    float shift = be[c_out] - mean*scale;

    float* outp = g_act1 + ((n*64 + c_out) << 10);
    outp[(by*2+0)*32 + bx*2+0] = lrelu(acc[0]*scale + shift);
    outp[(by*2+0)*32 + bx*2+1] = lrelu(acc[1]*scale + shift);
    outp[(by*2+1)*32 + bx*2+0] = lrelu(acc[2]*scale + shift);
    outp[(by*2+1)*32 + bx*2+1] = lrelu(acc[3]*scale + shift);
}

// ============================================================================
// conv2: act1(256,64,32,32) * w2(128,64,5,5) s2 p2 -> (256,128,16,16), IN+lrelu
// block = (16 c_outs, n); 256 threads; thread = (cg: 4 c_outs) x (2x2 quad).
// weights staged in chunks of 16 input channels. LDS:FMA = 8/16.
// ============================================================================
__global__ void __launch_bounds__(256) conv2_kernel(
    const float* __restrict__ w, const float* __restrict__ b,
    const float* __restrict__ g, const float* __restrict__ be)
{
    const int c0 = blockIdx.x * 16;           // gridDim.x = 8
    const int n  = blockIdx.y;
    const int tid = threadIdx.x;
    const int cg = tid >> 6;                  // 0..3 -> c_outs c0+cg*4+u
    const int q  = tid & 63;
    const int by = q >> 3, bx = q & 7;        // 8x8 quads over 16x16 plane

    __shared__ float s_in[36*36];
    __shared__ float s_w[16*16*25];           // [clo][dc][tap] = 6400
    __shared__ float s_r[256];
    __shared__ float s_q[256];

    float acc[4][4];
    #pragma unroll
    for (int u = 0; u < 4; ++u)
        #pragma unroll
        for (int p = 0; p < 4; ++p) acc[u][p] = 0.f;

    const float* inbase = g_act1 + ((n*64) << 10);

    for (int cc = 0; cc < 64; cc += 16) {
        __syncthreads();
        for (int idx = tid; idx < 6400; idx += 256) {
            int clo = idx / 400;
            int r = idx - clo*400;
            s_w[idx] = w[(c0 + clo)*1600 + cc*25 + r];
        }
        for (int c = 0; c < 16; ++c) {
            __syncthreads();
            const float* xp = inbase + ((cc + c) << 10);
            for (int idx = tid; idx < 36*36; idx += 256) {
                int sy = idx / 36 - 2;
                int sx = idx - (sy + 2)*36 - 2;
                float v = 0.f;
                if (sy >= 0 && sy < 32 && sx >= 0 && sx < 32) v = xp[(sy << 5) + sx];
                s_in[idx] = v;
            }
            __syncthreads();
            const float* tin = s_in + (by*4)*36 + bx*4;
            const float* tw  = s_w + (cg*4)*400 + c*25;
            #pragma unroll
            for (int ky = 0; ky < 5; ++ky) {
                #pragma unroll
                for (int kx = 0; kx < 5; ++kx) {
                    float i00 = tin[ky*36 + kx];
                    float i01 = tin[ky*36 + kx + 2];
                    float i10 = tin[(ky+2)*36 + kx];
                    float i11 = tin[(ky+2)*36 + kx + 2];
                    #pragma unroll
                    for (int u = 0; u < 4; ++u) {
                        float wv = tw[u*400 + ky*5 + kx];
                        acc[u][0] += i00*wv; acc[u][1] += i01*wv;
                        acc[u][2] += i10*wv; acc[u][3] += i11*wv;
                    }
                }
            }
        }
    }

    #pragma unroll
    for (int u = 0; u < 4; ++u) {
        int co = c0 + cg*4 + u;
        float bc = b[co];
        float lv = 0.f, lq = 0.f;
        #pragma unroll
        for (int p = 0; p < 4; ++p) { acc[u][p] += bc; lv += acc[u][p]; lq += acc[u][p]*acc[u][p]; }
        __syncthreads();
        s_r[tid] = lv; s_q[tid] = lq;
        __syncthreads();
        for (int s = 32; s > 0; s >>= 1) {
            if (q < s) { s_r[tid] += s_r[tid+s]; s_q[tid] += s_q[tid+s]; }
            __syncthreads();
        }
        float mean = s_r[cg << 6] * (1.f/256.f);
        float var  = fmaxf(s_q[cg << 6] * (1.f/256.f) - mean*mean, 0.f);
        float scale = g[co] * rsqrtf(var + EPS);
        float shift = be[co] - mean*scale;
        float* p0 = g_act2 + ((n*128 + co) << 8);
        p0[(by*2+0)*16 + bx*2+0] = lrelu(acc[u][0]*scale + shift);
        p0[(by*2+0)*16 + bx*2+1] = lrelu(acc[u][1]*scale + shift);
        p0[(by*2+1)*16 + bx*2+0] = lrelu(acc[u][2]*scale + shift);
        p0[(by*2+1)*16 + bx*2+1] = lrelu(acc[u][3]*scale + shift);
    }
}

// ============================================================================
// conv3: act2(256,128,16,16) * w3(256,128,5,5) s2 p2 -> (256,256,8,8), IN+lrelu
// block = (16 c_outs, n); 64 threads; thread = (cg: 4 c_outs) x (2x2 quad).
// ============================================================================
__global__ void __launch_bounds__(64) conv3_kernel(
    const float* __restrict__ w, const float* __restrict__ b,
    const float* __restrict__ g, const float* __restrict__ be)
{
    const int c0 = blockIdx.x * 16;           // gridDim.x = 16
    const int n  = blockIdx.y;
    const int tid = threadIdx.x;              // 64
    const int cg = tid >> 4;                  // 0..3 -> c_outs c0+cg*4+u
    const int qd = tid & 15;
    const int by = qd >> 2, bx = qd & 3;      // 4x4 quads over 8x8 plane

    __shared__ float s_in[20*20];
    __shared__ float s_w[16*16*25];           // [clo][dc][tap] = 6400

    float acc[4][4];
    #pragma unroll
    for (int u = 0; u < 4; ++u)
        #pragma unroll
        for (int p = 0; p < 4; ++p) acc[u][p] = 0.f;

    const float* inbase = g_act2 + ((n*128) << 8);

    for (int cc = 0; cc < 128; cc += 16) {
        __syncthreads();
        for (int idx = tid; idx < 6400; idx += 64) {
            int clo = idx / 400;
            int r = idx - clo*400;
            s_w[idx] = w[(c0 + clo)*3200 + cc*25 + r];
        }
        for (int c = 0; c < 16; ++c) {
            __syncthreads();
            const float* xp = inbase + ((cc + c) << 8);
            for (int idx = tid; idx < 400; idx += 64) {
                int sy = idx / 20 - 2;
                int sx = idx - (sy + 2)*20 - 2;
                float v = 0.f;
                if (sy >= 0 && sy < 16 && sx >= 0 && sx < 16) v = xp[(sy << 4) + sx];
                s_in[idx] = v;
            }
            __syncthreads();
            const float* tin = s_in + (by*4)*20 + bx*4;
            const float* tw  = s_w + (cg*4)*400 + c*25;
            #pragma unroll
            for (int ky = 0; ky < 5; ++ky) {
                #pragma unroll
                for (int kx = 0; kx < 5; ++kx) {
                    float i00 = tin[ky*20 + kx];
                    float i01 = tin[ky*20 + kx + 2];
                    float i10 = tin[(ky+2)*20 + kx];
                    float i11 = tin[(ky+2)*20 + kx + 2];
                    #pragma unroll
                    for (int u = 0; u < 4; ++u) {
                        float wv = tw[u*400 + ky*5 + kx];
                        acc[u][0] += i00*wv; acc[u][1] += i01*wv;
                        acc[u][2] += i10*wv; acc[u][3] += i11*wv;
                    }
                }
            }
        }
    }

    #pragma unroll
    for (int u = 0; u < 4; ++u) {
        int co = c0 + cg*4 + u;
        float bc = b[co];
        float lv = 0.f, lq = 0.f;
        #pragma unroll
        for (int p = 0; p < 4; ++p) { acc[u][p] += bc; lv += acc[u][p]; lq += acc[u][p]*acc[u][p]; }
        // reduce over the 16 threads (lanes) that own this plane
        #pragma unroll
        for (int off = 8; off >= 1; off >>= 1) {
            lv += __shfl_xor_sync(0xffffffffu, lv, off);
            lq += __shfl_xor_sync(0xffffffffu, lq, off);
        }
        float mean = lv * (1.f/64.f);
        float var  = fmaxf(lq * (1.f/64.f) - mean*mean, 0.f);
        float scale = g[co] * rsqrtf(var + EPS);
        float shift = be[co] - mean*scale;
        float* p0 = g_act3 + ((n*256 + co) << 6);
        p0[(by*2+0)*8 + bx*2+0] = lrelu(acc[u][0]*scale + shift);
        p0[(by*2+0)*8 + bx*2+1] = lrelu(acc[u][1]*scale + shift);
        p0[(by*2+1)*8 + bx*2+0] = lrelu(acc[u][2]*scale + shift);
        p0[(by*2+1)*8 + bx*2+1] = lrelu(acc[u][3]*scale + shift);
    }
}

// ============================================================================
// conv4: act3(256,256,8,8) * w4(256,256,3,3) s2 p1 -> (256,256,4,4), IN+lrelu
// writes feat directly into d_out. block = (64 c_outs, n); 256 threads;
// thread = (cq: 4 c_outs) x (1 pixel). channel chunks of 8.
// ============================================================================
__global__ void __launch_bounds__(256) conv4_kernel(
    const float* __restrict__ w, const float* __restrict__ b,
    const float* __restrict__ g, const float* __restrict__ be,
    float* __restrict__ feat)
{
    const int c0 = blockIdx.x * 64;           // gridDim.x = 4
    const int n  = blockIdx.y;
    const int tid = threadIdx.x;
    const int cq = tid >> 4;                  // 0..15 -> c_outs c0+cq*4+u
    const int pix = tid & 15;
    const int oy = pix >> 2, ox = pix & 3;

    __shared__ float s_in[8*100];             // 8 channels, padded 10x10
    __shared__ float s_w[64*8*9];             // [clo][cl][tap] = 4608

    float acc[4] = {0.f, 0.f, 0.f, 0.f};
    const float* inbase = g_act3 + ((n*256) << 6);

    for (int cc = 0; cc < 256; cc += 8) {
        __syncthreads();
        for (int idx = tid; idx < 800; idx += 256) {
            int cl = idx / 100;
            int r = idx - cl*100;
            int sy = r / 10 - 1;
            int sx = r - (sy + 1)*10 - 1;
            float v = 0.f;
            if (sy >= 0 && sy < 8 && sx >= 0 && sx < 8)
                v = inbase[((cc + cl) << 6) + (sy << 3) + sx];
            s_in[idx] = v;
        }
        for (int idx = tid; idx < 4608; idx += 256) {
            int clo = idx / 72;
            int r = idx - clo*72;
            int cl = r / 9;
            int t = r - cl*9;
            s_w[idx] = w[((c0 + clo)*256 + cc + cl)*9 + t];
        }
        __syncthreads();
        #pragma unroll
        for (int cl = 0; cl < 8; ++cl) {
            const float* tin = s_in + cl*100 + (oy*2)*10 + ox*2;
            float iv[9];
            #pragma unroll
            for (int ky = 0; ky < 3; ++ky)
                #pragma unroll
                for (int kx = 0; kx < 3; ++kx) iv[ky*3+kx] = tin[ky*10 + kx];
            #pragma unroll
            for (int u = 0; u < 4; ++u) {
                const float* tw = s_w + (cq*4 + u)*72 + cl*9;
                #pragma unroll
                for (int t = 0; t < 9; ++t) acc[u] += iv[t]*tw[t];
            }
        }
    }

    #pragma unroll
    for (int u = 0; u < 4; ++u) {
        int co = c0 + cq*4 + u;
        float v = acc[u] + b[co];
        float lv = v, lq = v*v;
        #pragma unroll
        for (int off = 8; off >= 1; off >>= 1) {
            lv += __shfl_xor_sync(0xffffffffu, lv, off);
            lq += __shfl_xor_sync(0xffffffffu, lq, off);
        }
        float mean = lv * (1.f/16.f);
        float var  = fmaxf(lq * (1.f/16.f) - mean*mean, 0.f);
        float scale = g[co] * rsqrtf(var + EPS);
        float shift = be[co] - mean*scale;
        feat[n*4096 + (co << 4) + pix] = lrelu(v*scale + shift);
    }
}

// ============================================================================
// M = feat(256x4096) @ T(4096x3200)  (T row-major == (4096,64,50) contiguous)
// 64x64x16 tiles, 256 threads, 4x4 per thread.
// ============================================================================
__global__ void __launch_bounds__(256) gemmM_kernel(
    const float* __restrict__ A, const float* __restrict__ B)
{
    const int n0 = blockIdx.x * 64;   // 0..49
    const int m0 = blockIdx.y * 64;   // 0..3
    const int tid = threadIdx.x;
    const int tx = tid & 15, ty = tid >> 4;

    __shared__ float sA[16*65];
    __shared__ float sB[16*64];

    float acc[4][4];
    #pragma unroll
    for (int i = 0; i < 4; ++i)
        #pragma unroll
        for (int j = 0; j < 4; ++j) acc[i][j] = 0.f;

    const int lrow = tid >> 2;          // 0..63
    const int lkk  = (tid & 3) << 2;    // 0,4,8,12
    const int bk   = tid >> 4;          // 0..15
    const int bj   = (tid & 15) << 2;   // 0..60

    for (int kt = 0; kt < 4096; kt += 16) {
        float4 va = *(const float4*)(A + (m0 + lrow)*4096 + kt + lkk);
        float4 vb = *(const float4*)(B + (kt + bk)*3200 + n0 + bj);
        sA[(lkk+0)*65 + lrow] = va.x;
        sA[(lkk+1)*65 + lrow] = va.y;
        sA[(lkk+2)*65 + lrow] = va.z;
        sA[(lkk+3)*65 + lrow] = va.w;
        *(float4*)(sB + bk*64 + bj) = vb;
        __syncthreads();
        #pragma unroll
        for (int k = 0; k < 16; ++k) {
            float a[4], bb[4];
            #pragma unroll
            for (int i = 0; i < 4; ++i) a[i]  = sA[k*65 + ty*4 + i];
            #pragma unroll
            for (int j = 0; j < 4; ++j) bb[j] = sB[k*64 + tx*4 + j];
            #pragma unroll
            for (int i = 0; i < 4; ++i)
                #pragma unroll
                for (int j = 0; j < 4; ++j) acc[i][j] += a[i]*bb[j];
        }
        __syncthreads();
    }
    #pragma unroll
    for (int i = 0; i < 4; ++i)
        #pragma unroll
        for (int j = 0; j < 4; ++j)
            g_M[(m0 + ty*4 + i)*3200 + n0 + tx*4 + j] = acc[i][j];
}

// ============================================================================
// o_b[j,o] = sum_i exp(-sum_k |M[i,o,k]-M[j,o,k]|) - 1
// ============================================================================
__global__ void __launch_bounds__(256) ob_kernel()
{
    const int o = blockIdx.x;     // 0..63
    const int j = blockIdx.y;     // 0..255
    const int tid = threadIdx.x;  // i = tid

    __shared__ float s_mj[50];
    __shared__ float s_red[256];

    if (tid < 50) s_mj[tid] = g_M[j*3200 + o*50 + tid];
    __syncthreads();

    const float* mi = g_M + tid*3200 + o*50;
    float d = 0.f;
    #pragma unroll
    for (int k = 0; k < 50; ++k) d += fabsf(mi[k] - s_mj[k]);
    s_red[tid] = expf(-d);
    __syncthreads();
    for (int s = 128; s > 0; s >>= 1) {
        if (tid < s) s_red[tid] += s_red[tid+s];
        __syncthreads();
    }
    if (tid == 0) g_ob[j*64 + o] = s_red[0] - 1.0f;
}

// ============================================================================
// mb = concat(feat, o_b) -> (256, 4160)
// ============================================================================
__global__ void __launch_bounds__(256) mbcat_kernel(const float* __restrict__ feat)
{
    int idx = blockIdx.x*256 + threadIdx.x;
    if (idx >= 256*4160) return;
    int bq = idx / 4160;
    int r  = idx - bq*4160;
    g_mb[idx] = (r < 4096) ? feat[bq*4096 + r] : g_ob[bq*64 + (r - 4096)];
}

// ============================================================================
// y = mb(256x4160) @ fc_w(1000x4160)^T + fc_b  (NT GEMM)
// ============================================================================
__global__ void __launch_bounds__(256) fc_kernel(
    const float* __restrict__ Wt, const float* __restrict__ bias,
    float* __restrict__ y)
{
    const int n0 = blockIdx.x * 64;   // 0..15 (covers 1000 with guard)
    const int m0 = blockIdx.y * 64;   // 0..3
    const int tid = threadIdx.x;
    const int tx = tid & 15, ty = tid >> 4;

    __shared__ float sA[16*65];
    __shared__ float sB[16*65];

    float acc[4][4];
    #pragma unroll
    for (int i = 0; i < 4; ++i)
        #pragma unroll
        for (int j = 0; j < 4; ++j) acc[i][j] = 0.f;

    const int lrow = tid >> 2;
    const int lkk  = (tid & 3) << 2;
    const bool bvalid = (n0 + lrow) < 1000;

    for (int kt = 0; kt < 4160; kt += 16) {
        float4 va = *(const float4*)(g_mb + (m0 + lrow)*4160 + kt + lkk);
        float4 vb = make_float4(0.f, 0.f, 0.f, 0.f);
        if (bvalid) vb = *(const float4*)(Wt + (n0 + lrow)*4160 + kt + lkk);
        sA[(lkk+0)*65 + lrow] = va.x;
        sA[(lkk+1)*65 + lrow] = va.y;
        sA[(lkk+2)*65 + lrow] = va.z;
        sA[(lkk+3)*65 + lrow] = va.w;
        sB[(lkk+0)*65 + lrow] = vb.x;
        sB[(lkk+1)*65 + lrow] = vb.y;
        sB[(lkk+2)*65 + lrow] = vb.z;
        sB[(lkk+3)*65 + lrow] = vb.w;
        __syncthreads();
        #pragma unroll
        for (int k = 0; k < 16; ++k) {
            float a[4], bb[4];
            #pragma unroll
            for (int i = 0; i < 4; ++i) a[i]  = sA[k*65 + ty*4 + i];
            #pragma unroll
            for (int j = 0; j < 4; ++j) bb[j] = sB[k*65 + tx*4 + j];
            #pragma unroll
            for (int i = 0; i < 4; ++i)
                #pragma unroll
                for (int j = 0; j < 4; ++j) acc[i][j] += a[i]*bb[j];
        }
        __syncthreads();
    }
    #pragma unroll
    for (int i = 0; i < 4; ++i) {
        #pragma unroll
        for (int j = 0; j < 4; ++j) {
            int nn = n0 + tx*4 + j;
            if (nn < 1000)
                y[(m0 + ty*4 + i)*1000 + nn] = acc[i][j] + bias[nn];
        }
    }
}

// ============================================================================
extern "C" void kernel_launch(void* const* d_in, const int* in_sizes, int n_in,
                              void* d_out, int out_size)
{
    (void)in_sizes; (void)n_in; (void)out_size;
    const float* x    = (const float*)d_in[0];
    const float* w1   = (const float*)d_in[1];
    const float* b1   = (const float*)d_in[2];
    const float* g1   = (const float*)d_in[3];
    const float* be1  = (const float*)d_in[4];
    const float* w2   = (const float*)d_in[5];
    const float* b2   = (const float*)d_in[6];
    const float* g2   = (const float*)d_in[7];
    const float* be2  = (const float*)d_in[8];
    const float* w3   = (const float*)d_in[9];
    const float* b3   = (const float*)d_in[10];
    const float* g3   = (const float*)d_in[11];
    const float* be3  = (const float*)d_in[12];
    const float* w4   = (const float*)d_in[13];
    const float* b4   = (const float*)d_in[14];
    const float* g4   = (const float*)d_in[15];
    const float* be4  = (const float*)d_in[16];
    const float* T    = (const float*)d_in[17];
    const float* fc_w = (const float*)d_in[18];
    const float* fc_b = (const float*)d_in[19];

    float* out  = (float*)d_out;
    float* feat = out;                    // (256, 4096)
    float* y    = out + 256*4096;         // (256, 1000)

    conv1_kernel<<<dim3(64, 256), 256>>>(x, w1, b1, g1, be1);
    conv2_kernel<<<dim3(8, 256), 256>>>(w2, b2, g2, be2);
    conv3_kernel<<<dim3(16, 256), 64>>>(w3, b3, g3, be3);
    conv4_kernel<<<dim3(4, 256), 256>>>(w4, b4, g4, be4, feat);
    gemmM_kernel<<<dim3(50, 4), 256>>>(feat, T);
    ob_kernel<<<dim3(64, 256), 256>>>();
    mbcat_kernel<<<4160, 256>>>(feat);
    fc_kernel<<<dim3(16, 4), 256>>>(fc_w, fc_b, y);
}